// round 2
// baseline (speedup 1.0000x reference)
#include <cuda_runtime.h>

// Embedding gather: out[row, :] = weight[ids[row], :]
// ids: [8192] int32, weight: [32000, 1024] f32, out: [8192, 1024] f32.
//
// Latency-bound fix: R=8 rows per CTA so each thread issues 8 independent
// LDG.128 gathers (MLP=8) instead of 1. 256 threads x float4 covers one
// 1024-float row per row-slot.

#define DIM   1024
#define VEC   (DIM / 4)   // 256 float4 per row
#define ROWS  8           // rows per CTA

__global__ void __launch_bounds__(256, 8)
embed_gather_kernel(const int* __restrict__ ids,
                    const float* __restrict__ weight,
                    float* __restrict__ out)
{
    const int base = blockIdx.x * ROWS;
    const int t    = threadIdx.x;

    // 8 ids, uniform across the CTA (broadcast loads, L1-resident).
    const int4 i0 = __ldg(reinterpret_cast<const int4*>(ids + base));
    const int4 i1 = __ldg(reinterpret_cast<const int4*>(ids + base + 4));

    const float4* __restrict__ w = reinterpret_cast<const float4*>(weight);
    float4* __restrict__ o       = reinterpret_cast<float4*>(out);

    // 8 independent gathers in flight.
    float4 v0 = __ldg(w + (size_t)i0.x * VEC + t);
    float4 v1 = __ldg(w + (size_t)i0.y * VEC + t);
    float4 v2 = __ldg(w + (size_t)i0.z * VEC + t);
    float4 v3 = __ldg(w + (size_t)i0.w * VEC + t);
    float4 v4 = __ldg(w + (size_t)i1.x * VEC + t);
    float4 v5 = __ldg(w + (size_t)i1.y * VEC + t);
    float4 v6 = __ldg(w + (size_t)i1.z * VEC + t);
    float4 v7 = __ldg(w + (size_t)i1.w * VEC + t);

    size_t ob = (size_t)base * VEC + t;
    o[ob + 0 * VEC] = v0;
    o[ob + 1 * VEC] = v1;
    o[ob + 2 * VEC] = v2;
    o[ob + 3 * VEC] = v3;
    o[ob + 4 * VEC] = v4;
    o[ob + 5 * VEC] = v5;
    o[ob + 6 * VEC] = v6;
    o[ob + 7 * VEC] = v7;
}

extern "C" void kernel_launch(void* const* d_in, const int* in_sizes, int n_in,
                              void* d_out, int out_size)
{
    const int*   ids    = (const int*)d_in[0];
    const float* weight = (const float*)d_in[1];
    float*       out    = (float*)d_out;

    const int n_rows = in_sizes[0];         // 8192
    const int grid   = n_rows / ROWS;       // 1024

    embed_gather_kernel<<<grid, 256>>>(ids, weight, out);
}